// round 10
// baseline (speedup 1.0000x reference)
#include <cuda_runtime.h>
#include <cuda_fp16.h>
#include <cstdint>
#include <math.h>

// ---------------- problem constants ----------------
#define BATCH 8192
#define IN_F  1024
#define OUT_F 1024
#define NB    8
#define KTOT  9216                       // 1024 (silu) + 8192 (basis)

// ---------------- GEMM tiling (fp16 HMMA m16n8k16) ----------------
#define BM 128
#define BN 256
#define BK 64                            // 64 halfs = 128 bytes = one SW128 row
#define STAGES 4
#define NITER (KTOT / BK)                // 144
#define NSILU 16                         // first 16 stages come from g_As
#define STAGE_BYTES ((BM + BN) * 128)    // 49152
#define BB_OFF (BM * 128)                // 16384
#define SMEM_DYN (STAGES * STAGE_BYTES)  // 196608

// scratch (allocation-free rule: __device__ globals)
__device__ __half g_As[(size_t)BATCH * IN_F];   // 16 MB  (silu slice only)
__device__ __half g_W[(size_t)OUT_F * KTOT];    // 19 MB

// ---------------- helpers ----------------
__device__ __forceinline__ uint32_t smem_u32(const void* p) {
    uint32_t a;
    asm("{ .reg .u64 t; cvta.to.shared.u64 t, %1; cvt.u32.u64 %0, t; }" : "=r"(a) : "l"(p));
    return a;
}

#define SWZ(o) ((o) ^ (((o) >> 3) & 0x70))

__device__ __forceinline__ void cp16(uint32_t dst, const void* src) {
    asm volatile("cp.async.cg.shared.global [%0], [%1], 16;"
                 :: "r"(dst), "l"(__cvta_generic_to_global(src)));
}
#define CP_COMMIT() asm volatile("cp.async.commit_group;" ::: "memory")
#define CP_WAIT_2() asm volatile("cp.async.wait_group 2;" ::: "memory")

#define LDSM4(r, addr) \
    asm volatile("ldmatrix.sync.aligned.m8n8.x4.shared.b16 {%0,%1,%2,%3}, [%4];" \
        : "=r"((r)[0]), "=r"((r)[1]), "=r"((r)[2]), "=r"((r)[3]) : "r"(addr))

// m16n8k16 fp16 MMA, fp32 accumulate (sm_80+ baseline — legal on plain sm_103)
__device__ __forceinline__ void mma_f16(float* c, const uint32_t* a,
                                        uint32_t b0, uint32_t b1) {
    asm volatile(
        "mma.sync.aligned.m16n8k16.row.col.f32.f16.f16.f32 "
        "{%0,%1,%2,%3}, {%4,%5,%6,%7}, {%8,%9}, {%0,%1,%2,%3};"
        : "+f"(c[0]), "+f"(c[1]), "+f"(c[2]), "+f"(c[3])
        : "r"(a[0]), "r"(a[1]), "r"(a[2]), "r"(a[3]), "r"(b0), "r"(b1));
}

// FMA-only SiLU. exp(-|v|) via range reduction + deg-4 2^u poly + exponent
// splice; 1/(1+e) via Newton with seed valid on d in [1,2]:
//   r0 = 24/17 - 8/17*d  (max rel err 1/17; two steps -> ~1.2e-5).
// (R9 bug: used the [0.5,1]-range seed 48/17 - 32/17*d, negative for d>1.5.)
__device__ __forceinline__ float silu_fma(float v) {
    float av = fminf(fabsf(v), 80.0f);
    float y = av * 1.4426950408889634f;          // av * log2(e)
    float n = floorf(y + 0.5f);
    float u = n - y;                             // u in [-0.5, 0.5]; 2^{-y} = 2^u * 2^{-n}
    float p = fmaf(u, 0.0096181291f, 0.0555041087f);
    p = fmaf(u, p, 0.2402265069f);
    p = fmaf(u, p, 0.6931471806f);
    p = fmaf(u, p, 1.0f);                        // 2^u
    int ni = (int)n;
    float s = __int_as_float((127 - ni) << 23);  // 2^{-n}
    float e = p * s;                             // exp(-av), in (0, 1]
    float d = 1.0f + e;                          // (1, 2]
    float r = fmaf(d, -0.470588235f, 1.411764706f);  // 24/17 - 8/17*d
    r = r * (2.0f - d * r);
    r = r * (2.0f - d * r);                      // 1/(1+e)
    float sig = (v >= 0.0f) ? r : (1.0f - r);    // sigmoid(v)
    return v * sig;
}

// Cubic B-spline weights for clipped x. seg in 0..5; nonzero bases seg..seg+3.
__device__ __forceinline__ void bspline_w(float xv, int& seg,
                                          float& w0, float& w1, float& w2, float& w3) {
    float xc = fminf(fmaxf(xv, -1.0f), 1.0f);
    seg = min((int)floorf((xc + 1.0f) * 2.5f), 5);   // >=0 since xc>=-1
    float t = fmaf(2.5f, xc, 2.5f - (float)seg);     // (xc+1)*2.5 - seg, in [0,1]
    float t2 = t * t, t3 = t2 * t;
    float omt = 1.0f - t;
    const float c6 = 1.0f / 6.0f;
    w0 = omt * omt * omt * c6;
    w1 = (3.0f * t3 - 6.0f * t2 + 4.0f) * c6;
    w2 = (-3.0f * t3 + 3.0f * t2 + 3.0f * t + 1.0f) * c6;
    w3 = t3 * c6;                                    // == 0 when seg==5 (t==0)
}

// =====================================================================
// P0: g_As = h(silu(x))  (8192 x 1024), FMA-only, 8 elems/thread
// =====================================================================
__global__ void prep_silu_kernel(const float* __restrict__ x) {
    size_t base = ((size_t)blockIdx.x * blockDim.x + threadIdx.x) * 8;
    float4 f0 = *(const float4*)(x + base);
    float4 f1 = *(const float4*)(x + base + 4);
    __half h[8];
    h[0] = __float2half_rn(silu_fma(f0.x)); h[1] = __float2half_rn(silu_fma(f0.y));
    h[2] = __float2half_rn(silu_fma(f0.z)); h[3] = __float2half_rn(silu_fma(f0.w));
    h[4] = __float2half_rn(silu_fma(f1.x)); h[5] = __float2half_rn(silu_fma(f1.y));
    h[6] = __float2half_rn(silu_fma(f1.z)); h[7] = __float2half_rn(silu_fma(f1.w));
    *(uint4*)(g_As + base) = *(const uint4*)h;
}

// =====================================================================
// P1: W = [ h(base_weight) | h(spline_weight) ]  (O, 9216), 8 elems/thread
// =====================================================================
__global__ void prep_W_kernel(const float* __restrict__ bw, const float* __restrict__ sw) {
    int o = blockIdx.y;
    int k8 = (blockIdx.x * blockDim.x + threadIdx.x) * 8;
    const float* src = (k8 < IN_F) ? (bw + (size_t)o * IN_F + k8)
                                   : (sw + (size_t)o * (IN_F * NB) + (k8 - IN_F));
    float4 f0 = *(const float4*)(src);
    float4 f1 = *(const float4*)(src + 4);
    __half h[8];
    h[0] = __float2half_rn(f0.x); h[1] = __float2half_rn(f0.y);
    h[2] = __float2half_rn(f0.z); h[3] = __float2half_rn(f0.w);
    h[4] = __float2half_rn(f1.x); h[5] = __float2half_rn(f1.y);
    h[6] = __float2half_rn(f1.z); h[7] = __float2half_rn(f1.w);
    *(uint4*)(g_W + (size_t)o * KTOT + k8) = *(const uint4*)h;
}

// =====================================================================
// GEMM with fused basis producer.
// A column space: k<1024 -> silu (cp.async from g_As); k>=1024 -> basis chunk
// of 8 halfs computed in-kernel from one x value (k = 1024 + 8*i + j).
// Stage L>=16 covers x indices ii0..ii0+7, ii0 = 8*L - 128.
// =====================================================================
__global__ __launch_bounds__(256, 1)
void kan_gemm_kernel(float* __restrict__ out, const float* __restrict__ x) {
    extern __shared__ char smem[];
    uint32_t sb = smem_u32(smem);
    int tid = threadIdx.x;
    int wid = tid >> 5;
    int lid = tid & 31;
    int n0 = blockIdx.x * BN;
    int m0 = blockIdx.y * BM;

    // ---- producer addressing ----
    // chunk grid: row = rb + 32u (u=0..3 for A), 16B col = cb
    int rb = tid >> 3, cb = tid & 7;
    size_t asoff = (size_t)(m0 + rb) * IN_F + cb * 8;    // silu slice, halfs
    size_t boff  = (size_t)(n0 + rb) * KTOT + cb * 8;    // W, halfs
    uint32_t s0 = SWZ((uint32_t)(rb * 128 + cb * 16));   // +4096 per 32 rows (swizzle-safe)
    const float* xbase = x + (size_t)(m0 + rb) * IN_F + cb;  // + u*32*IN_F + ii0

    auto load_B = [&](int L) {
        uint32_t base = sb + (uint32_t)(L & (STAGES - 1)) * STAGE_BYTES;
        size_t kb = (size_t)L * BK;
#pragma unroll
        for (int u = 0; u < 8; u++)                      // B: 256 rows x 8 chunks
            cp16(base + BB_OFF + s0 + u * 4096, g_W + boff + (size_t)u * 32 * KTOT + kb);
    };
    auto load_A_silu = [&](int L) {
        uint32_t base = sb + (uint32_t)(L & (STAGES - 1)) * STAGE_BYTES;
        size_t kb = (size_t)L * BK;                      // < 1024
#pragma unroll
        for (int u = 0; u < 4; u++)                      // A: 128 rows x 8 chunks
            cp16(base + s0 + u * 4096, g_As + asoff + (size_t)u * 32 * IN_F + kb);
    };
    auto store_A_basis = [&](int L, const float* xq) {
        uint32_t base = sb + (uint32_t)(L & (STAGES - 1)) * STAGE_BYTES;
#pragma unroll
        for (int u = 0; u < 4; u++) {
            int seg; float w0, w1, w2, w3;
            bspline_w(xq[u], seg, w0, w1, w2, w3);
            uint32_t ca = base + s0 + u * 4096;          // this thread's 16B chunk
            asm volatile("st.shared.v4.b32 [%0], {%1,%1,%1,%1};" :: "r"(ca), "r"(0u) : "memory");
            uint32_t da = ca + (uint32_t)(seg * 2);      // intra-chunk: swizzle-invariant
            unsigned short h0 = __half_as_ushort(__float2half_rn(w0));
            unsigned short h1 = __half_as_ushort(__float2half_rn(w1));
            unsigned short h2 = __half_as_ushort(__float2half_rn(w2));
            unsigned short h3 = __half_as_ushort(__float2half_rn(w3));
            asm volatile("st.shared.u16 [%0], %1;" :: "r"(da), "h"(h0) : "memory");
            asm volatile("st.shared.u16 [%0], %1;" :: "r"(da + 2), "h"(h1) : "memory");
            asm volatile("st.shared.u16 [%0], %1;" :: "r"(da + 4), "h"(h2) : "memory");
            if (seg < 5)                                  // seg==5 -> w3==0, slot j=8 absent
                asm volatile("st.shared.u16 [%0], %1;" :: "r"(da + 6), "h"(h3) : "memory");
        }
    };

    // ---- consumer addressing ----
    int wm = (wid >> 2) * 64;
    int wn = (wid & 3) * 64;
    int arow = ((lid & 8) ? 8 : 0) + (lid & 7);
    int akg  = (lid & 16) ? 16 : 0;
    int brow = ((lid & 16) ? 8 : 0) + (lid & 7);
    int bkg  = (lid & 8) ? 16 : 0;

    float acc[4][8][4];
#pragma unroll
    for (int mi = 0; mi < 4; mi++)
#pragma unroll
        for (int ni = 0; ni < 8; ni++)
#pragma unroll
            for (int v = 0; v < 4; v++) acc[mi][ni][v] = 0.0f;

    // ---- pipeline prologue: stages 0..2 (all silu region, pure cp.async) ----
    load_A_silu(0); load_B(0); CP_COMMIT();
    load_A_silu(1); load_B(1); CP_COMMIT();
    load_A_silu(2); load_B(2); CP_COMMIT();

    float xq[4];                                          // x prefetch for next fused stage

    for (int i = 0; i < NITER; i++) {
        CP_WAIT_2();                 // stage i's cp.async complete (this thread)
        __syncthreads();             // all copies/STS visible; buf (i-1)%4 free for reuse
        int L = i + 3;
        if (L < NITER) {
            load_B(L);
            if (L < NSILU) load_A_silu(L);
            else           store_A_basis(L, xq);          // uses xq from previous iter
        }
        CP_COMMIT();                 // uniform group count

        int Lp = i + 4;              // prefetch x for next iter's fused stage
        if (Lp >= NSILU && Lp < NITER) {
            int ii0 = Lp * 8 - 128;
#pragma unroll
            for (int u = 0; u < 4; u++)
                xq[u] = __ldg(xbase + (size_t)u * 32 * IN_F + ii0);
        }

        uint32_t stg = sb + (uint32_t)(i & 3) * STAGE_BYTES;
#pragma unroll
        for (int s = 0; s < 4; s++) {            // 4 x k16 steps = BK 64
            uint32_t a[4][4], b[4][4];
#pragma unroll
            for (int mi = 0; mi < 4; mi++) {
                uint32_t ad = stg + SWZ((uint32_t)((wm + mi * 16 + arow) * 128 + s * 32 + akg));
                LDSM4(a[mi], ad);
            }
#pragma unroll
            for (int p = 0; p < 4; p++) {
                uint32_t bd = stg + BB_OFF +
                              SWZ((uint32_t)((wn + p * 16 + brow) * 128 + s * 32 + bkg));
                LDSM4(b[p], bd);
            }
#pragma unroll
            for (int mi = 0; mi < 4; mi++)
#pragma unroll
                for (int ni = 0; ni < 8; ni++)
                    mma_f16(acc[mi][ni], a[mi],
                            b[ni >> 1][(ni & 1) * 2], b[ni >> 1][(ni & 1) * 2 + 1]);
        }
    }

    // ---- epilogue ----
    int er = m0 + wm + (lid >> 2);
    int ec = n0 + wn + (lid & 3) * 2;
#pragma unroll
    for (int mi = 0; mi < 4; mi++) {
#pragma unroll
        for (int ni = 0; ni < 8; ni++) {
            float2 v0 = make_float2(acc[mi][ni][0], acc[mi][ni][1]);
            float2 v1 = make_float2(acc[mi][ni][2], acc[mi][ni][3]);
            *(float2*)(out + (size_t)(er + mi * 16) * OUT_F + ec + ni * 8) = v0;
            *(float2*)(out + (size_t)(er + mi * 16 + 8) * OUT_F + ec + ni * 8) = v1;
        }
    }
}

// =====================================================================
extern "C" void kernel_launch(void* const* d_in, const int* in_sizes, int n_in,
                              void* d_out, int out_size) {
    const float* x  = (const float*)d_in[0];   // (8192, 1024)
    const float* bw = (const float*)d_in[1];   // (1024, 1024)
    const float* sw = (const float*)d_in[2];   // (1024, 1024, 8)
    float* out = (float*)d_out;                // (8192, 1024)

    prep_silu_kernel<<<(BATCH * IN_F / 8) / 256, 256>>>(x);
    prep_W_kernel<<<dim3(KTOT / 8 / 128, OUT_F), 128>>>(bw, sw);

    cudaFuncSetAttribute(kan_gemm_kernel, cudaFuncAttributeMaxDynamicSharedMemorySize, SMEM_DYN);
    kan_gemm_kernel<<<dim3(OUT_F / BN, BATCH / BM), 256, SMEM_DYN>>>(out, x);
}

// round 11
// speedup vs baseline: 1.0259x; 1.0259x over previous
#include <cuda_runtime.h>
#include <cuda_fp16.h>
#include <cstdint>
#include <math.h>

// ---------------- problem constants ----------------
#define BATCH 8192
#define IN_F  1024
#define OUT_F 1024
#define NB    8
#define KTOT  9216                       // 1024 (silu) + 8192 (basis)

// ---------------- GEMM tiling (fp16 HMMA m16n8k16) ----------------
#define BM 128
#define BN 256
#define BK 64                            // 64 halfs = 128 bytes = one SW128 row
#define STAGES 4
#define NITER (KTOT / BK)                // 144
#define STAGE_BYTES ((BM + BN) * 128)    // 49152
#define BB_OFF (BM * 128)                // 16384
#define SMEM_DYN (STAGES * STAGE_BYTES)  // 196608

// scratch (allocation-free rule: __device__ globals)
__device__ __half g_A[(size_t)BATCH * KTOT];   // 151 MB  (full fused A)
__device__ __half g_W[(size_t)OUT_F * KTOT];   //  19 MB

// ---------------- helpers ----------------
__device__ __forceinline__ uint32_t smem_u32(const void* p) {
    uint32_t a;
    asm("{ .reg .u64 t; cvta.to.shared.u64 t, %1; cvt.u32.u64 %0, t; }" : "=r"(a) : "l"(p));
    return a;
}

#define SWZ(o) ((o) ^ (((o) >> 3) & 0x70))

__device__ __forceinline__ void cp16(uint32_t dst, const void* src) {
    asm volatile("cp.async.cg.shared.global [%0], [%1], 16;"
                 :: "r"(dst), "l"(__cvta_generic_to_global(src)));
}
#define CP_COMMIT() asm volatile("cp.async.commit_group;" ::: "memory")
#define CP_WAIT_2() asm volatile("cp.async.wait_group 2;" ::: "memory")

#define LDSM4(r, addr) \
    asm volatile("ldmatrix.sync.aligned.m8n8.x4.shared.b16 {%0,%1,%2,%3}, [%4];" \
        : "=r"((r)[0]), "=r"((r)[1]), "=r"((r)[2]), "=r"((r)[3]) : "r"(addr))

// m16n8k16 fp16 MMA, fp32 accumulate (sm_80+ baseline — legal on plain sm_103)
__device__ __forceinline__ void mma_f16(float* c, const uint32_t* a,
                                        uint32_t b0, uint32_t b1) {
    asm volatile(
        "mma.sync.aligned.m16n8k16.row.col.f32.f16.f16.f32 "
        "{%0,%1,%2,%3}, {%4,%5,%6,%7}, {%8,%9}, {%0,%1,%2,%3};"
        : "+f"(c[0]), "+f"(c[1]), "+f"(c[2]), "+f"(c[3])
        : "r"(a[0]), "r"(a[1]), "r"(a[2]), "r"(a[3]), "r"(b0), "r"(b1));
}

// FMA-only SiLU. exp(-|v|) via range reduction + deg-4 2^u poly + exponent
// splice; 1/(1+e) via Newton, seed valid on d in [1,2]: r0 = 24/17 - 8/17*d.
__device__ __forceinline__ float silu_fma(float v) {
    float av = fminf(fabsf(v), 80.0f);
    float y = av * 1.4426950408889634f;          // av * log2(e)
    float n = floorf(y + 0.5f);
    float u = n - y;                             // [-0.5,0.5]; 2^{-y} = 2^u * 2^{-n}
    float p = fmaf(u, 0.0096181291f, 0.0555041087f);
    p = fmaf(u, p, 0.2402265069f);
    p = fmaf(u, p, 0.6931471806f);
    p = fmaf(u, p, 1.0f);                        // 2^u
    float s = __int_as_float((127 - (int)n) << 23);  // 2^{-n}
    float e = p * s;                             // exp(-av), (0,1]
    float d = 1.0f + e;                          // (1,2]
    float r = fmaf(d, -0.470588235f, 1.411764706f);  // 24/17 - 8/17*d
    r = r * (2.0f - d * r);
    r = r * (2.0f - d * r);                      // 1/(1+e)
    float sig = (v >= 0.0f) ? r : (1.0f - r);
    return v * sig;
}

// =====================================================================
// P0: g_A = [ h(silu(x)) | h(cubic basis(clip(x))) ]  per row, FMA-only.
// Closed-form uniform cubic B-spline (verified vs reference in R8):
// seg = floor((xc+1)*2.5) clamped to 5; bases seg..seg+3 get
// {(1-t)^3, 3t^3-6t^2+4, -3t^3+3t^2+3t+1, t^3}/6; seg=5 -> t=0 -> w3=0.
// =====================================================================
__global__ void prep_A_kernel(const float* __restrict__ x) {
    int b = blockIdx.y;
    int i = blockIdx.x * blockDim.x + threadIdx.x;   // 0..1023
    float v = x[(size_t)b * IN_F + i];
    __half* row = g_A + (size_t)b * KTOT;

    row[i] = __float2half_rn(silu_fma(v));

    float xc = fminf(fmaxf(v, -1.0f), 1.0f);
    int seg = min((int)floorf((xc + 1.0f) * 2.5f), 5);
    float t = fmaf(2.5f, xc, 2.5f - (float)seg);     // in [0,1]
    float t2 = t * t, t3 = t2 * t;
    float omt = 1.0f - t;
    const float c6 = 1.0f / 6.0f;
    float w0 = omt * omt * omt * c6;
    float w1 = (3.0f * t3 - 6.0f * t2 + 4.0f) * c6;
    float w2 = (-3.0f * t3 + 3.0f * t2 + 3.0f * t + 1.0f) * c6;
    float w3 = t3 * c6;

    __half h[8];
#pragma unroll
    for (int j = 0; j < 8; j++) h[j] = __ushort_as_half((unsigned short)0);
    h[seg]     = __float2half_rn(w0);
    h[seg + 1] = __float2half_rn(w1);
    h[seg + 2] = __float2half_rn(w2);
    if (seg + 3 < 8) h[seg + 3] = __float2half_rn(w3);  // seg==5: w3==0, slot absent

    *(uint4*)(row + IN_F + (size_t)i * NB) = *(const uint4*)h;   // 16B aligned
}

// =====================================================================
// P1: W = [ h(base_weight) | h(spline_weight) ]  (O, 9216), 8 elems/thread
// =====================================================================
__global__ void prep_W_kernel(const float* __restrict__ bw, const float* __restrict__ sw) {
    int o = blockIdx.y;
    int k8 = (blockIdx.x * blockDim.x + threadIdx.x) * 8;
    const float* src = (k8 < IN_F) ? (bw + (size_t)o * IN_F + k8)
                                   : (sw + (size_t)o * (IN_F * NB) + (k8 - IN_F));
    float4 f0 = *(const float4*)(src);
    float4 f1 = *(const float4*)(src + 4);
    __half h[8];
    h[0] = __float2half_rn(f0.x); h[1] = __float2half_rn(f0.y);
    h[2] = __float2half_rn(f0.z); h[3] = __float2half_rn(f0.w);
    h[4] = __float2half_rn(f1.x); h[5] = __float2half_rn(f1.y);
    h[6] = __float2half_rn(f1.z); h[7] = __float2half_rn(f1.w);
    *(uint4*)(g_W + (size_t)o * KTOT + k8) = *(const uint4*)h;
}

// =====================================================================
// GEMM: out[m,n] = sum_k A[m,k] * W[n,k]
// fp16 m16n8k16, BM=128 x BN=256, 8 warps (2x4), warp tile 64x64,
// 4-stage cp.async pipeline + DOUBLE-BUFFERED ldmatrix fragments:
// step s+1's 8 LDSMs issue before step s's 64 MMAs (drain LDS latency
// under the MMA stream — the R8 loop exposed it at 2 warps/SMSP).
// =====================================================================
__global__ __launch_bounds__(256, 1)
void kan_gemm_kernel(float* __restrict__ out) {
    extern __shared__ char smem[];
    uint32_t sb = smem_u32(smem);
    int tid = threadIdx.x;
    int wid = tid >> 5;
    int lid = tid & 31;
    int n0 = blockIdx.x * BN;
    int m0 = blockIdx.y * BM;

    // ---- producer addressing: 12 x 16B chunks / thread / stage ----
    int rb = tid >> 3, cb = tid & 7;
    size_t aoff = (size_t)(m0 + rb) * KTOT + cb * 8;     // halfs
    size_t boff = (size_t)(n0 + rb) * KTOT + cb * 8;
    uint32_t s0 = SWZ((uint32_t)(rb * 128 + cb * 16));   // +4096 per 32 rows (swizzle-safe)

    auto load_stage = [&](int L) {
        uint32_t base = sb + (uint32_t)(L & (STAGES - 1)) * STAGE_BYTES;
        size_t kb = (size_t)L * BK;
#pragma unroll
        for (int u = 0; u < 4; u++)                      // A: 128 rows x 8 chunks
            cp16(base + s0 + u * 4096, g_A + aoff + (size_t)u * 32 * KTOT + kb);
#pragma unroll
        for (int u = 0; u < 8; u++)                      // B: 256 rows x 8 chunks
            cp16(base + BB_OFF + s0 + u * 4096, g_W + boff + (size_t)u * 32 * KTOT + kb);
    };

    // ---- consumer addressing ----
    int wm = (wid >> 2) * 64;
    int wn = (wid & 3) * 64;
    int arow = ((lid & 8) ? 8 : 0) + (lid & 7);
    int akg  = (lid & 16) ? 16 : 0;
    int brow = ((lid & 16) ? 8 : 0) + (lid & 7);
    int bkg  = (lid & 8) ? 16 : 0;

    float acc[4][8][4];
#pragma unroll
    for (int mi = 0; mi < 4; mi++)
#pragma unroll
        for (int ni = 0; ni < 8; ni++)
#pragma unroll
            for (int v = 0; v < 4; v++) acc[mi][ni][v] = 0.0f;

    uint32_t af[2][4][4], bf[2][4][4];

    // ---- pipeline ----
    load_stage(0); CP_COMMIT();
    load_stage(1); CP_COMMIT();
    load_stage(2); CP_COMMIT();

    for (int i = 0; i < NITER; i++) {
        CP_WAIT_2();                 // stage i resident (this thread's copies)
        __syncthreads();             // all copies visible; buf (i-1)%4 reads done
        if (i + 3 < NITER) load_stage(i + 3);
        CP_COMMIT();                 // uniform group count

        uint32_t stg = sb + (uint32_t)(i & 3) * STAGE_BYTES;

        // prime fragments for s=0
#pragma unroll
        for (int mi = 0; mi < 4; mi++)
            LDSM4(af[0][mi], stg + SWZ((uint32_t)((wm + mi * 16 + arow) * 128 + akg)));
#pragma unroll
        for (int p = 0; p < 4; p++)
            LDSM4(bf[0][p], stg + BB_OFF + SWZ((uint32_t)((wn + p * 16 + brow) * 128 + bkg)));

#pragma unroll
        for (int s = 0; s < 4; s++) {            // 4 x k16 steps = BK 64
            int cur = s & 1, nxt = cur ^ 1;
            if (s < 3) {                          // prefetch s+1 before s's MMAs
#pragma unroll
                for (int mi = 0; mi < 4; mi++)
                    LDSM4(af[nxt][mi], stg + SWZ((uint32_t)((wm + mi * 16 + arow) * 128
                                                            + (s + 1) * 32 + akg)));
#pragma unroll
                for (int p = 0; p < 4; p++)
                    LDSM4(bf[nxt][p], stg + BB_OFF + SWZ((uint32_t)((wn + p * 16 + brow) * 128
                                                                    + (s + 1) * 32 + bkg)));
            }
#pragma unroll
            for (int mi = 0; mi < 4; mi++)
#pragma unroll
                for (int ni = 0; ni < 8; ni++)
                    mma_f16(acc[mi][ni], af[cur][mi],
                            bf[cur][ni >> 1][(ni & 1) * 2], bf[cur][ni >> 1][(ni & 1) * 2 + 1]);
        }
    }

    // ---- epilogue: c frag m16n8 f32: rows {t/4, t/4+8}, cols {2*(t%4), +1} ----
    int er = m0 + wm + (lid >> 2);
    int ec = n0 + wn + (lid & 3) * 2;
#pragma unroll
    for (int mi = 0; mi < 4; mi++) {
#pragma unroll
        for (int ni = 0; ni < 8; ni++) {
            float2 v0 = make_float2(acc[mi][ni][0], acc[mi][ni][1]);
            float2 v1 = make_float2(acc[mi][ni][2], acc[mi][ni][3]);
            *(float2*)(out + (size_t)(er + mi * 16) * OUT_F + ec + ni * 8) = v0;
            *(float2*)(out + (size_t)(er + mi * 16 + 8) * OUT_F + ec + ni * 8) = v1;
        }
    }
}

// =====================================================================
extern "C" void kernel_launch(void* const* d_in, const int* in_sizes, int n_in,
                              void* d_out, int out_size) {
    const float* x  = (const float*)d_in[0];   // (8192, 1024)
    const float* bw = (const float*)d_in[1];   // (1024, 1024)
    const float* sw = (const float*)d_in[2];   // (1024, 1024, 8)
    float* out = (float*)d_out;                // (8192, 1024)

    prep_A_kernel<<<dim3(IN_F / 256, BATCH), 256>>>(x);
    prep_W_kernel<<<dim3(KTOT / 8 / 128, OUT_F), 128>>>(bw, sw);

    cudaFuncSetAttribute(kan_gemm_kernel, cudaFuncAttributeMaxDynamicSharedMemorySize, SMEM_DYN);
    kan_gemm_kernel<<<dim3(OUT_F / BN, BATCH / BM), 256, SMEM_DYN>>>(out);
}